// round 8
// baseline (speedup 1.0000x reference)
#include <cuda_runtime.h>

// out[i, j] = filt[i] * x[i, j].  Nominal: x [8192, 4096] fp32, filt [8192] fp32.
// Pure HBM-streaming kernel: 16B vectorized, fully coalesced.
// Sizes derived from in_sizes at launch time for robustness.
// Each thread handles 2 independent float4s (split total/2 apart) for MLP=2.

__global__ __launch_bounds__(256) void diag_scale_kernel(
    const float4* __restrict__ x,
    const float* __restrict__ filt,
    float4* __restrict__ out,
    int half_f4,        // total float4 count / 2
    int row_f4_shift)   // log2(float4 per row)
{
    int idx = blockIdx.x * blockDim.x + threadIdx.x;
    if (idx >= half_f4) return;
    int idx2 = idx + half_f4;

    // filt is L2-resident (32 KB) and warp-broadcast: issue first so the
    // multiply chain arms while the DRAM float4 loads are in flight.
    float f0 = __ldg(&filt[idx >> row_f4_shift]);
    float f1 = __ldg(&filt[idx2 >> row_f4_shift]);
    float4 v0 = x[idx];
    float4 v1 = x[idx2];

    v0.x *= f0; v0.y *= f0; v0.z *= f0; v0.w *= f0;
    v1.x *= f1; v1.y *= f1; v1.z *= f1; v1.w *= f1;

    out[idx]  = v0;
    out[idx2] = v1;
}

// Fallback for non-vectorizable / odd shapes (not expected to be used).
__global__ __launch_bounds__(256) void diag_scale_scalar_kernel(
    const float* __restrict__ x,
    const float* __restrict__ filt,
    float* __restrict__ out,
    int total, int m)
{
    int idx = blockIdx.x * blockDim.x + threadIdx.x;
    if (idx >= total) return;
    out[idx] = x[idx] * __ldg(&filt[idx / m]);
}

extern "C" void kernel_launch(void* const* d_in, const int* in_sizes, int n_in,
                              void* d_out, int out_size)
{
    const float* x    = (const float*)d_in[0];
    const float* filt = (const float*)d_in[1];
    float* out        = (float*)d_out;

    int total  = in_sizes[0];        // n * m
    int n_filt = in_sizes[1];        // n
    int m      = total / n_filt;     // 4096 nominally

    // Vector path requires m % 4 == 0 and (m/4) a power of two.
    int row_f4 = m >> 2;
    bool pow2 = (m % 4 == 0) && ((row_f4 & (row_f4 - 1)) == 0);
    int total_f4 = total >> 2;

    if (pow2 && (total_f4 % 2 == 0)) {
        int half_f4 = total_f4 >> 1;
        int shift = 0;
        while ((1 << shift) < row_f4) shift++;
        int threads = 256;
        int blocks = (half_f4 + threads - 1) / threads;
        diag_scale_kernel<<<blocks, threads>>>(
            (const float4*)x, filt, (float4*)out, half_f4, shift);
    } else {
        int threads = 256;
        int blocks = (total + threads - 1) / threads;
        diag_scale_scalar_kernel<<<blocks, threads>>>(x, filt, out, total, m);
    }
}

// round 9
// speedup vs baseline: 1.0360x; 1.0360x over previous
#include <cuda_runtime.h>

// out[i, j] = filt[i] * x[i, j].  Nominal: x [8192, 4096] fp32, filt [8192] fp32.
// One CTA = one 1024-float4 tile inside a single row (m=4096 -> tile == row).
// Each thread: 4 independent float4 loads front-batched (MLP=4), one broadcast
// filt scalar per block. Streaming cache hints: data is touched exactly once.

__global__ __launch_bounds__(256) void diag_scale_row4(
    const float4* __restrict__ x,
    const float* __restrict__ filt,
    float4* __restrict__ out,
    int tiles_per_row_shift)     // log2(row_f4 / 1024)
{
    int tile = blockIdx.x;
    int row  = tile >> tiles_per_row_shift;
    float f  = __ldg(&filt[row]);            // L1-hit broadcast, one per block

    int base = (tile << 10) + threadIdx.x;   // tile * 1024 + tid

    // Front-batch all 4 loads (independent, evict-first).
    float4 v0 = __ldcs(&x[base]);
    float4 v1 = __ldcs(&x[base + 256]);
    float4 v2 = __ldcs(&x[base + 512]);
    float4 v3 = __ldcs(&x[base + 768]);

    v0.x *= f; v0.y *= f; v0.z *= f; v0.w *= f;
    v1.x *= f; v1.y *= f; v1.z *= f; v1.w *= f;
    v2.x *= f; v2.y *= f; v2.z *= f; v2.w *= f;
    v3.x *= f; v3.y *= f; v3.z *= f; v3.w *= f;

    __stcs(&out[base],       v0);
    __stcs(&out[base + 256], v1);
    __stcs(&out[base + 512], v2);
    __stcs(&out[base + 768], v3);
}

// Fallback for shapes that don't tile to 1024 float4 per row chunk.
__global__ __launch_bounds__(256) void diag_scale_scalar_kernel(
    const float* __restrict__ x,
    const float* __restrict__ filt,
    float* __restrict__ out,
    int total, int m)
{
    int idx = blockIdx.x * blockDim.x + threadIdx.x;
    if (idx >= total) return;
    out[idx] = x[idx] * __ldg(&filt[idx / m]);
}

extern "C" void kernel_launch(void* const* d_in, const int* in_sizes, int n_in,
                              void* d_out, int out_size)
{
    const float* x    = (const float*)d_in[0];
    const float* filt = (const float*)d_in[1];
    float* out        = (float*)d_out;

    int total  = in_sizes[0];        // n * m
    int n_filt = in_sizes[1];        // n
    int m      = total / n_filt;     // 4096 nominally

    int row_f4 = m >> 2;             // float4 per row (1024 nominal)
    // Fast path: m % 4 == 0, row_f4 a power-of-two multiple of 1024.
    bool fast = (m % 4 == 0) && (row_f4 >= 1024) && ((row_f4 & (row_f4 - 1)) == 0);

    if (fast) {
        int tiles_per_row = row_f4 >> 10;           // power of two
        int shift = 0;
        while ((1 << shift) < tiles_per_row) shift++;
        int blocks = n_filt * tiles_per_row;        // 8192 nominal
        diag_scale_row4<<<blocks, 256>>>(
            (const float4*)x, filt, (float4*)out, shift);
    } else {
        int threads = 256;
        int blocks = (total + threads - 1) / threads;
        diag_scale_scalar_kernel<<<blocks, threads>>>(x, filt, out, total, m);
    }
}